// round 6
// baseline (speedup 1.0000x reference)
#include <cuda_runtime.h>
#include <cuda_bf16.h>
#include <cstddef>
#include <cstdint>

// Problem constants (B=4096, n=512, m=1024)
#define Bsz 4096
#define Nn  512
#define Mm  1024
#define STEPC 0.01f
#define TOLV 1e-5f

// ---- tensor-core PGD tile config ----
#define TM 128
#define TN 256
#define KC 64
#define NCH (Mm / KC)          // 16 K-chunks
#define TILEA_B 16384          // 128x64 bf16 tile bytes
#define TILEB_B 32768          // 256x64 bf16 tile bytes
#define OFF_ALO 16384
#define OFF_BHI 32768
#define OFF_BLO 65536
#define STG_SZ  98304          // 96 KB per stage
#define DSMEM   (2 * STG_SZ + 1024)
#define NCTA    128

// tcgen05 is arch-specific: only present in the sm_103a device pass.
#if defined(__CUDA_ARCH__) && defined(__CUDA_ARCH_FEAT_SM103_ALL)
#define HAS_TCGEN05 1
#else
#define HAS_TCGEN05 0
#endif

// ---------------- device scratch (allocation-free) ----------------
__device__ __align__(128) float g_Q[Mm * Mm];
__device__ __align__(128) float g_xu[Bsz * Nn];
__device__ __align__(128) float g_c[(size_t)Bsz * Mm];
__device__ __align__(128) float g_msk[(size_t)Bsz * Mm];
__device__ __align__(128) float g_act[(size_t)Bsz * Mm];
__device__ __align__(128) float g_z[Bsz * Nn];
__device__ __align__(128) float g_lamf[(size_t)Bsz * Mm];
// tiled + pre-swizzled operand images (SW128 SMEM image, contiguous per tile)
__device__ __align__(128) __nv_bfloat16 g_Qhi[Mm * Mm];          // [4 nb][16 ch][256x64]
__device__ __align__(128) __nv_bfloat16 g_Qlo[Mm * Mm];
__device__ __align__(128) __nv_bfloat16 g_lAhi[(size_t)Bsz * Mm]; // [32 bm][16 ch][128x64]
__device__ __align__(128) __nv_bfloat16 g_lAlo[(size_t)Bsz * Mm];
__device__ __align__(128) __nv_bfloat16 g_lBhi[(size_t)Bsz * Mm];
__device__ __align__(128) __nv_bfloat16 g_lBlo[(size_t)Bsz * Mm];
// software grid barrier state
__device__ unsigned g_bar_cnt = 0;
__device__ unsigned g_bar_gen = 0;

// ---------------- PTX helpers (generic; safe on all targets) ----------------
__device__ __forceinline__ uint32_t s2u(const void* p) {
    uint32_t a;
    asm("{ .reg .u64 t; cvta.to.shared.u64 t, %1; cvt.u32.u64 %0, t; }"
        : "=r"(a) : "l"(p));
    return a;
}

__device__ __forceinline__ uint32_t swz(uint32_t off) {
    return off ^ ((off >> 3) & 0x70);
}

__device__ __forceinline__ void mbar_init(uint32_t a, uint32_t cnt) {
    asm volatile("mbarrier.init.shared.b64 [%0], %1;" :: "r"(a), "r"(cnt) : "memory");
}

// arrive + expect tx
__device__ __forceinline__ void mbar_arrive_tx(uint32_t a, uint32_t bytes) {
    asm volatile("mbarrier.arrive.expect_tx.shared.b64 _, [%0], %1;"
                 :: "r"(a), "r"(bytes) : "memory");
}
// expect tx WITHOUT arrive (split accounting)
__device__ __forceinline__ void mbar_tx_only(uint32_t a, uint32_t bytes) {
    asm volatile("mbarrier.expect_tx.shared.b64 [%0], %1;"
                 :: "r"(a), "r"(bytes) : "memory");
}

__device__ __forceinline__ void mbar_wait(uint32_t a, uint32_t phase) {
    uint32_t done = 0;
    while (!done) {
        asm volatile(
            "{ .reg .pred p; mbarrier.try_wait.parity.shared.b64 p, [%1], %2; "
            "selp.b32 %0, 1, 0, p; }"
            : "=r"(done) : "r"(a), "r"(phase) : "memory");
    }
}

// bulk async copy: contiguous GMEM -> SMEM, completion via mbarrier tx bytes
__device__ __forceinline__ void bulk_g2s(uint32_t dst, const void* src,
                                         uint32_t bytes, uint32_t mbar) {
    asm volatile(
        "cp.async.bulk.shared::cluster.global.mbarrier::complete_tx::bytes "
        "[%0], [%1], %2, [%3];"
        :: "r"(dst), "l"(src), "r"(bytes), "r"(mbar) : "memory");
}

// gpu-scope software grid barrier (all CTAs co-resident)
__device__ __forceinline__ void grid_sync() {
    __syncthreads();
    if (threadIdx.x == 0) {
        unsigned* cnt = &g_bar_cnt;
        unsigned* gen = &g_bar_gen;
        unsigned g;
        asm volatile("ld.acquire.gpu.u32 %0, [%1];" : "=r"(g) : "l"(gen));
        unsigned old;
        asm volatile("atom.add.release.gpu.u32 %0, [%1], 1;"
                     : "=r"(old) : "l"(cnt) : "memory");
        if (old == NCTA - 1) {
            asm volatile("st.relaxed.gpu.u32 [%0], 0;" :: "l"(cnt) : "memory");
            asm volatile("red.add.release.gpu.u32 [%0], 1;" :: "l"(gen) : "memory");
        } else {
            unsigned cur;
            do {
                asm volatile("ld.acquire.gpu.u32 %0, [%1];" : "=r"(cur) : "l"(gen));
            } while (cur == g);
        }
    }
    __syncthreads();
}

// SW128 K-major SMEM descriptor (LBO=1, SBO=64, version=1, layout=SW128)
__device__ __forceinline__ uint64_t mkdesc(uint32_t addr) {
    return ((uint64_t)2 << 61) | ((uint64_t)1 << 46) | ((uint64_t)64 << 32)
         | ((uint64_t)1 << 16) | ((addr >> 4) & 0x3FFF);
}

// idesc kind::f16: dtype=F32, atype=btype=BF16, N=TN, M=128
#define PGD_IDESC ((1u<<4) | (1u<<7) | (1u<<10) | ((TN/8)<<17) | ((128/16)<<24))

__device__ __forceinline__ float bfbits2f(uint16_t u) {
    __nv_bfloat16_raw r; r.x = u;
    return __bfloat162float(__nv_bfloat16(r));
}
__device__ __forceinline__ uint16_t f2bfbits(float f) {
    __nv_bfloat16 h = __float2bfloat16(f);
    __nv_bfloat16_raw r = (__nv_bfloat16_raw)h;
    return r.x;
}

#if HAS_TCGEN05
// ---------------- tcgen05 helpers (sm_103a pass only) ----------------
__device__ __forceinline__ void mma_f16_ss(uint32_t d, uint64_t a, uint64_t b,
                                           uint32_t idesc, uint32_t en) {
    asm volatile(
        "{\n\t.reg .pred p;\n\tsetp.ne.u32 p, %5, 0;\n\t"
        "tcgen05.mma.cta_group::1.kind::f16 [%0], %1, %2, %3, {%4,%4,%4,%4}, p;\n\t}"
        :: "r"(d), "l"(a), "l"(b), "r"(idesc), "r"(0u), "r"(en) : "memory");
}

__device__ __forceinline__ void tc_commit(uint32_t mbar) {
    asm volatile(
        "tcgen05.commit.cta_group::1.mbarrier::arrive::one.shared::cluster.b64 [%0];"
        :: "r"(mbar) : "memory");
}

#define TC_ALLOC(sres, n) \
    asm volatile("tcgen05.alloc.cta_group::1.sync.aligned.shared::cta.b32 [%0], %1;" \
                 :: "r"(sres), "r"((uint32_t)(n)) : "memory")
#define TC_RELINQ() \
    asm volatile("tcgen05.relinquish_alloc_permit.cta_group::1.sync.aligned;")
#define TC_DEALLOC(t, n) \
    asm volatile("tcgen05.dealloc.cta_group::1.sync.aligned.b32 %0, %1;" :: "r"(t), "r"((uint32_t)(n)))
#define TC_FENCE_AFTER()  asm volatile("tcgen05.fence::after_thread_sync;" ::: "memory")
#define TC_FENCE_BEFORE() asm volatile("tcgen05.fence::before_thread_sync;" ::: "memory")
#define TC_WAIT_LD()      asm volatile("tcgen05.wait::ld.sync.aligned;" ::: "memory")

#define LDTM_X32(r, a) \
    asm volatile( \
        "tcgen05.ld.sync.aligned.32x32b.x32.b32 " \
        "{%0,%1,%2,%3,%4,%5,%6,%7,%8,%9,%10,%11,%12,%13,%14,%15," \
        "%16,%17,%18,%19,%20,%21,%22,%23,%24,%25,%26,%27,%28,%29,%30,%31}, [%32];" \
        : "=r"((r)[0]),"=r"((r)[1]),"=r"((r)[2]),"=r"((r)[3]), \
          "=r"((r)[4]),"=r"((r)[5]),"=r"((r)[6]),"=r"((r)[7]), \
          "=r"((r)[8]),"=r"((r)[9]),"=r"((r)[10]),"=r"((r)[11]), \
          "=r"((r)[12]),"=r"((r)[13]),"=r"((r)[14]),"=r"((r)[15]), \
          "=r"((r)[16]),"=r"((r)[17]),"=r"((r)[18]),"=r"((r)[19]), \
          "=r"((r)[20]),"=r"((r)[21]),"=r"((r)[22]),"=r"((r)[23]), \
          "=r"((r)[24]),"=r"((r)[25]),"=r"((r)[26]),"=r"((r)[27]), \
          "=r"((r)[28]),"=r"((r)[29]),"=r"((r)[30]),"=r"((r)[31]) \
        : "r"(a))
#endif  // HAS_TCGEN05

// ---------------------------------------------------------------------------
// Persistent tensor-core PGD: runs `nit` iterations in ONE launch.
//   lam ping-pongs between lA and lB tiled bf16 hi/lo images each iteration.
//   Q (B operand) is iteration-invariant: its next-iter chunks are prefetched
//   BEFORE the grid barrier (expect_tx without arrive); the lam (A) chunks are
//   issued after the barrier (arrive.expect_tx completes the phase).
// ---------------------------------------------------------------------------
__global__ void __launch_bounds__(256, 1) pgd_persist(
    __nv_bfloat16* __restrict__ lAhi, __nv_bfloat16* __restrict__ lAlo,
    __nv_bfloat16* __restrict__ lBhi, __nv_bfloat16* __restrict__ lBlo,
    const __nv_bfloat16* __restrict__ Qhi, const __nv_bfloat16* __restrict__ Qlo,
    const float* __restrict__ cc, const float* __restrict__ act,
    float* __restrict__ Of32, int nit, int masked)
{
#if HAS_TCGEN05
    extern __shared__ char draw[];
    const uint32_t dsm = (s2u(draw) + 1023u) & ~1023u;

    __shared__ uint32_t s_tmem;
    __shared__ __align__(8) uint64_t s_bar[5];   // full0, full1, empty0, empty1, done

    const int tid  = threadIdx.x;
    const int wid  = tid >> 5;
    const int lane = tid & 31;
    const int bm0  = blockIdx.y * TM;
    const int bn0  = blockIdx.x * TN;

    const uint32_t f0 = s2u(&s_bar[0]);
    const uint32_t f1 = s2u(&s_bar[1]);
    const uint32_t e0 = s2u(&s_bar[2]);
    const uint32_t e1 = s2u(&s_bar[3]);
    const uint32_t db = s2u(&s_bar[4]);

    if (wid == 0) TC_ALLOC(s2u(&s_tmem), 256);
    if (tid == 0) {
        mbar_init(f0, 1); mbar_init(f1, 1);
        mbar_init(e0, 1); mbar_init(e1, 1);
        mbar_init(db, 1);
    }
    __syncthreads();
    uint32_t tmem;
    asm volatile("ld.shared.b32 %0, [%1];" : "=r"(tmem) : "r"(s2u(&s_tmem)));

    const size_t yoffA = (size_t)blockIdx.y * 16 * TILEA_B;
    const char* bH = (const char*)Qhi + (size_t)blockIdx.x * 16 * TILEB_B;
    const char* bL = (const char*)Qlo + (size_t)blockIdx.x * 16 * TILEB_B;

    // tid0-private pipeline parity state (persists across iterations)
    uint32_t phf0 = 0, phf1 = 0, phe0 = 0, phe1 = 0;

    // prologue: full A+B loads for chunks 0,1 of iteration 1 (A source = lA)
    if (tid == 0) {
        const char* aH = (const char*)lAhi + yoffA;
        const char* aL = (const char*)lAlo + yoffA;
#pragma unroll
        for (int ch = 0; ch < 2; ch++) {
            const uint32_t fb = ch ? f1 : f0;
            const uint32_t st = dsm + (uint32_t)ch * STG_SZ;
            mbar_arrive_tx(fb, STG_SZ);
            bulk_g2s(st,           aH + (size_t)ch * TILEA_B, TILEA_B, fb);
            bulk_g2s(st + OFF_ALO, aL + (size_t)ch * TILEA_B, TILEA_B, fb);
            bulk_g2s(st + OFF_BHI, bH + (size_t)ch * TILEB_B, TILEB_B, fb);
            bulk_g2s(st + OFF_BLO, bL + (size_t)ch * TILEB_B, TILEB_B, fb);
        }
    }

#pragma unroll 1
    for (int it = 1; it <= nit; it++) {
        const int odd = it & 1;
        const __nv_bfloat16* rdH = odd ? lAhi : lBhi;
        const __nv_bfloat16* rdL = odd ? lAlo : lBlo;
        __nv_bfloat16* wrH = odd ? lBhi : lAhi;
        __nv_bfloat16* wrL = odd ? lBlo : lAlo;
        const int writeF32 = (it == nit);

        // ---------- tid0: mainloop ----------
        if (tid == 0) {
            const char* aH = (const char*)rdH + yoffA;
            const char* aL = (const char*)rdL + yoffA;
#pragma unroll 1
            for (int ch = 0; ch < NCH; ch++) {
                const int s = ch & 1;
                mbar_wait(s ? f1 : f0, s ? phf1 : phf0);
                if (s) phf1 ^= 1; else phf0 ^= 1;

                const uint32_t st = dsm + (uint32_t)s * STG_SZ;
                const uint64_t dah = mkdesc(st);
                const uint64_t dal = mkdesc(st + OFF_ALO);
                const uint64_t dbh = mkdesc(st + OFF_BHI);
                const uint64_t dbl = mkdesc(st + OFF_BLO);
#pragma unroll
                for (int ks = 0; ks < 4; ks++) {
                    mma_f16_ss(tmem, dah + ks * 2, dbh + ks * 2, PGD_IDESC,
                               (ch == 0 && ks == 0) ? 0u : 1u);
                    mma_f16_ss(tmem, dah + ks * 2, dbl + ks * 2, PGD_IDESC, 1u);
                    mma_f16_ss(tmem, dal + ks * 2, dbh + ks * 2, PGD_IDESC, 1u);
                }
                tc_commit(s ? e1 : e0);

                if (ch < NCH - 2) {
                    mbar_wait(s ? e1 : e0, s ? phe1 : phe0);
                    if (s) phe1 ^= 1; else phe0 ^= 1;
                    const int nx = ch + 2;
                    const uint32_t fb = s ? f1 : f0;
                    mbar_arrive_tx(fb, STG_SZ);
                    bulk_g2s(st,           aH + (size_t)nx * TILEA_B, TILEA_B, fb);
                    bulk_g2s(st + OFF_ALO, aL + (size_t)nx * TILEA_B, TILEA_B, fb);
                    bulk_g2s(st + OFF_BHI, bH + (size_t)nx * TILEB_B, TILEB_B, fb);
                    bulk_g2s(st + OFF_BLO, bL + (size_t)nx * TILEB_B, TILEB_B, fb);
                }
            }
            tc_commit(db);

            if (it < nit) {
                // stages free once last two chunks' MMAs complete
                mbar_wait(e0, phe0); phe0 ^= 1;
                mbar_wait(e1, phe1); phe1 ^= 1;
                // prefetch next-iter B (Q) chunks 0,1 — tx only, no arrive
                mbar_tx_only(f0, 2 * TILEB_B);
                bulk_g2s(dsm + OFF_BHI,          bH,                    TILEB_B, f0);
                bulk_g2s(dsm + OFF_BLO,          bL,                    TILEB_B, f0);
                mbar_tx_only(f1, 2 * TILEB_B);
                bulk_g2s(dsm + STG_SZ + OFF_BHI, bH + TILEB_B,          TILEB_B, f1);
                bulk_g2s(dsm + STG_SZ + OFF_BLO, bL + TILEB_B,          TILEB_B, f1);
            }
        }

        // ---------- all threads: wait MMA done, fused epilogue ----------
        mbar_wait(db, (uint32_t)((it - 1) & 1));
        TC_FENCE_AFTER();

        const int sp   = wid & 3;
        const int half = wid >> 2;
        const int lr   = sp * 32 + lane;
        const int r    = bm0 + lr;

#pragma unroll 1
        for (int cb = 0; cb < 128; cb += 32) {
            uint32_t dreg[32];
            LDTM_X32(dreg, tmem + half * 128 + cb);
            TC_WAIT_LD();

            const int coff  = half * 128 + cb;
            const int chunk = coff >> 6;
            const int gch   = (bn0 >> 6) + chunk;
            const int lc0   = coff & 63;
            const size_t tb = ((size_t)(blockIdx.y * 16 + gch)) * TILEA_B;
            const size_t blin = (size_t)r * Mm + bn0 + coff;

#pragma unroll
            for (int j0 = 0; j0 < 32; j0 += 4) {
                const uint32_t boff = swz((uint32_t)(lr * 128 + (lc0 + j0) * 2));
                float4 cv = *(const float4*)&cc[blin + j0];
                uint64_t h4 = *(const uint64_t*)((const char*)rdH + tb + boff);
                uint64_t l4 = *(const uint64_t*)((const char*)rdL + tb + boff);
                float4 av;
                if (masked) av = *(const float4*)&act[blin + j0];
                const float* cvp = (const float*)&cv;
                const float* avp = (const float*)&av;
                uint16_t oh[4], ol[4];
                float of[4];
#pragma unroll
                for (int k = 0; k < 4; k++) {
                    float lamold = bfbits2f((uint16_t)(h4 >> (16 * k)))
                                 + bfbits2f((uint16_t)(l4 >> (16 * k)));
                    float acc = __uint_as_float(dreg[j0 + k]);
                    float v = fmaxf(lamold - STEPC * (acc - cvp[k]), 0.f);
                    if (masked) v *= avp[k];
                    uint16_t hb = f2bfbits(v);
                    oh[k] = hb;
                    ol[k] = f2bfbits(v - bfbits2f(hb));
                    of[k] = v;
                }
                uint64_t ohp = (uint64_t)oh[0] | ((uint64_t)oh[1] << 16)
                             | ((uint64_t)oh[2] << 32) | ((uint64_t)oh[3] << 48);
                uint64_t olp = (uint64_t)ol[0] | ((uint64_t)ol[1] << 16)
                             | ((uint64_t)ol[2] << 32) | ((uint64_t)ol[3] << 48);
                *(uint64_t*)((char*)wrH + tb + boff) = ohp;
                *(uint64_t*)((char*)wrL + tb + boff) = olp;
                if (writeF32)
                    *(float4*)&Of32[blin + j0] = make_float4(of[0], of[1], of[2], of[3]);
            }
        }
        TC_FENCE_BEFORE();

        // ---------- iteration boundary ----------
        if (it < nit) {
            grid_sync();
            if (tid == 0) {
                // A (new lam) loads for next iteration chunks 0,1 — arrive + tx
                const char* nH = (const char*)wrH + yoffA;
                const char* nL = (const char*)wrL + yoffA;
                mbar_arrive_tx(f0, 2 * TILEA_B);
                bulk_g2s(dsm,                    nH,           TILEA_B, f0);
                bulk_g2s(dsm + OFF_ALO,          nL,           TILEA_B, f0);
                mbar_arrive_tx(f1, 2 * TILEA_B);
                bulk_g2s(dsm + STG_SZ,           nH + TILEA_B, TILEA_B, f1);
                bulk_g2s(dsm + STG_SZ + OFF_ALO, nL + TILEA_B, TILEA_B, f1);
            }
        }
    }

    __syncthreads();
    if (wid == 0) { TC_RELINQ(); TC_DEALLOC(tmem, 256); }
#endif  // HAS_TCGEN05
}

// ---------------------------------------------------------------------------
// fp32 SIMT SGEMM (peripheral GEMMs)
// ---------------------------------------------------------------------------
enum { EPI_NONE = 0, EPI_SUB_B, EPI_RES, EPI_ACTIVE, EPI_MASKED };

template <bool TB, int EPI>
__global__ void __launch_bounds__(256, 2) sgemm(
    const float* __restrict__ Ag, const float* __restrict__ Bg,
    float* __restrict__ Cg, int M, int N, int K,
    const float* __restrict__ e1)
{
    constexpr int BM = 128, BN = 128, BK = 16;
    __shared__ float As[BK][BM];
    __shared__ float Bs[BK][BN];

    const int tid  = threadIdx.x;
    const int bm0  = blockIdx.y * BM;
    const int bn0  = blockIdx.x * BN;
    const int cRow = (tid >> 4) * 8;
    const int cCol = (tid & 15) * 8;

    float acc[8][8];
#pragma unroll
    for (int i = 0; i < 8; i++)
#pragma unroll
        for (int j = 0; j < 8; j++) acc[i][j] = 0.f;

    for (int k0 = 0; k0 < K; k0 += BK) {
#pragma unroll
        for (int l = 0; l < 2; l++) {
            int f = tid + l * 256, row = f >> 2, c4 = f & 3;
            float4 v = *(const float4*)&Ag[(size_t)(bm0 + row) * K + k0 + c4 * 4];
            As[c4 * 4 + 0][row] = v.x; As[c4 * 4 + 1][row] = v.y;
            As[c4 * 4 + 2][row] = v.z; As[c4 * 4 + 3][row] = v.w;
        }
        if (TB) {
#pragma unroll
            for (int l = 0; l < 2; l++) {
                int f = tid + l * 256, row = f >> 2, c4 = f & 3;
                float4 v = *(const float4*)&Bg[(size_t)(bn0 + row) * K + k0 + c4 * 4];
                Bs[c4 * 4 + 0][row] = v.x; Bs[c4 * 4 + 1][row] = v.y;
                Bs[c4 * 4 + 2][row] = v.z; Bs[c4 * 4 + 3][row] = v.w;
            }
        } else {
#pragma unroll
            for (int l = 0; l < 2; l++) {
                int f = tid + l * 256, row = f >> 5, c4 = f & 31;
                float4 v = *(const float4*)&Bg[(size_t)(k0 + row) * N + bn0 + c4 * 4];
                *(float4*)&Bs[row][c4 * 4] = v;
            }
        }
        __syncthreads();
#pragma unroll
        for (int k = 0; k < BK; k++) {
            float4 a0 = *(const float4*)&As[k][cRow];
            float4 a1 = *(const float4*)&As[k][cRow + 4];
            float4 b0 = *(const float4*)&Bs[k][cCol];
            float4 b1 = *(const float4*)&Bs[k][cCol + 4];
            float a[8] = {a0.x, a0.y, a0.z, a0.w, a1.x, a1.y, a1.z, a1.w};
            float b[8] = {b0.x, b0.y, b0.z, b0.w, b1.x, b1.y, b1.z, b1.w};
#pragma unroll
            for (int i = 0; i < 8; i++)
#pragma unroll
                for (int j = 0; j < 8; j++) acc[i][j] += a[i] * b[j];
        }
        __syncthreads();
    }

#pragma unroll
    for (int i = 0; i < 8; i++) {
        const int r = bm0 + cRow + i;
#pragma unroll
        for (int j = 0; j < 8; j++) {
            const int cl = bn0 + cCol + j;
            const size_t idx = (size_t)r * N + cl;
            const float v = acc[i][j];
            if (EPI == EPI_NONE)        Cg[idx] = v;
            else if (EPI == EPI_SUB_B)  Cg[idx] = v - e1[cl];
            else if (EPI == EPI_RES)    Cg[idx] = e1[idx] - v;
            else if (EPI == EPI_ACTIVE) Cg[idx] = (v >= e1[cl] - TOLV) ? 1.f : 0.f;
            else if (EPI == EPI_MASKED) Cg[idx] = v * e1[idx];
        }
    }
}

// ---------------- small elementwise kernels ----------------
__global__ void add_kernel(const float* __restrict__ x, const float* __restrict__ u,
                           float* __restrict__ o, int n)
{
    int i = blockIdx.x * blockDim.x + threadIdx.x;
    if (i < n) o[i] = x[i] + u[i];
}

// split Q fp32 -> tiled/swizzled bf16 hi/lo B-image: tile (nb=row/256, ch=col/64)
__global__ void split_q_tiled(const float* __restrict__ s,
                              __nv_bfloat16* __restrict__ hi,
                              __nv_bfloat16* __restrict__ lo)
{
    int i = blockIdx.x * blockDim.x + threadIdx.x;
    if (i >= Mm * Mm) return;
    int qr = i >> 10, qc = i & 1023;
    int nb = qr >> 8, lrow = qr & 255, ch = qc >> 6, lc = qc & 63;
    size_t tb = ((size_t)(nb * 16 + ch)) * TILEB_B;
    uint32_t boff = swz((uint32_t)(lrow * 128 + lc * 2));
    float v = s[i];
    __nv_bfloat16 h = __float2bfloat16(v);
    *(__nv_bfloat16*)((char*)hi + tb + boff) = h;
    *(__nv_bfloat16*)((char*)lo + tb + boff) = __float2bfloat16(v - __bfloat162float(h));
}

// lam init -> tiled/swizzled A-image: tile (bm=row/128, ch=col/64)
__global__ void lam_init_tiled(const float* __restrict__ c,
                               __nv_bfloat16* __restrict__ hi,
                               __nv_bfloat16* __restrict__ lo)
{
    int i = blockIdx.x * blockDim.x + threadIdx.x;
    if (i >= Bsz * Mm) return;
    int r = i >> 10, cx = i & 1023;
    int bm = r >> 7, lrow = r & 127, ch = cx >> 6, lc = cx & 63;
    size_t tb = ((size_t)(bm * 16 + ch)) * TILEA_B;
    uint32_t boff = swz((uint32_t)(lrow * 128 + lc * 2));
    float v = fmaxf(STEPC * c[i], 0.f);
    __nv_bfloat16 h = __float2bfloat16(v);
    *(__nv_bfloat16*)((char*)hi + tb + boff) = h;
    *(__nv_bfloat16*)((char*)lo + tb + boff) = __float2bfloat16(v - __bfloat162float(h));
}

__global__ void lam_init_mask_tiled(const float* __restrict__ m, const float* __restrict__ a,
                                    __nv_bfloat16* __restrict__ hi,
                                    __nv_bfloat16* __restrict__ lo)
{
    int i = blockIdx.x * blockDim.x + threadIdx.x;
    if (i >= Bsz * Mm) return;
    int r = i >> 10, cx = i & 1023;
    int bm = r >> 7, lrow = r & 127, ch = cx >> 6, lc = cx & 63;
    size_t tb = ((size_t)(bm * 16 + ch)) * TILEA_B;
    uint32_t boff = swz((uint32_t)(lrow * 128 + lc * 2));
    float v = fmaxf(STEPC * m[i], 0.f) * a[i];
    __nv_bfloat16 h = __float2bfloat16(v);
    *(__nv_bfloat16*)((char*)hi + tb + boff) = h;
    *(__nv_bfloat16*)((char*)lo + tb + boff) = __float2bfloat16(v - __bfloat162float(h));
}

// ---------------------------------------------------------------------------
extern "C" void kernel_launch(void* const* d_in, const int* in_sizes, int n_in,
                              void* d_out, int out_size)
{
    const float* x = (const float*)d_in[0];
    const float* u = (const float*)d_in[1];
    const float* A = (const float*)d_in[2];   // [m, n]
    const float* b = (const float*)d_in[3];   // [m]
    float* out = (float*)d_out;

    float *Q, *xu, *c, *msk, *act, *z, *lamf;
    __nv_bfloat16 *Qhi, *Qlo, *lAhi, *lAlo, *lBhi, *lBlo;
    cudaGetSymbolAddress((void**)&Q,    g_Q);
    cudaGetSymbolAddress((void**)&xu,   g_xu);
    cudaGetSymbolAddress((void**)&c,    g_c);
    cudaGetSymbolAddress((void**)&msk,  g_msk);
    cudaGetSymbolAddress((void**)&act,  g_act);
    cudaGetSymbolAddress((void**)&z,    g_z);
    cudaGetSymbolAddress((void**)&lamf, g_lamf);
    cudaGetSymbolAddress((void**)&Qhi,  g_Qhi);
    cudaGetSymbolAddress((void**)&Qlo,  g_Qlo);
    cudaGetSymbolAddress((void**)&lAhi, g_lAhi);
    cudaGetSymbolAddress((void**)&lAlo, g_lAlo);
    cudaGetSymbolAddress((void**)&lBhi, g_lBhi);
    cudaGetSymbolAddress((void**)&lBlo, g_lBlo);

    cudaFuncSetAttribute(pgd_persist, cudaFuncAttributeMaxDynamicSharedMemorySize, DSMEM);

    const dim3 blk(256);
    const dim3 gQ(Mm / 128, Mm / 128);
    const dim3 gBm(Mm / 128, Bsz / 128);
    const dim3 gBn(Nn / 128, Bsz / 128);
    const dim3 gT(Mm / TN, Bsz / TM);        // 4 x 32 = 128 CTAs (one wave)
    const int EW = 256;

    // 1) Q = A @ A^T  (fp32)
    sgemm<true, EPI_NONE><<<gQ, blk>>>(A, A, Q, Mm, Mm, Nn, nullptr);
    // 2) split Q -> tiled/swizzled bf16 hi/lo
    split_q_tiled<<<(Mm * Mm) / EW, EW>>>(Q, Qhi, Qlo);
    // 3) xu = x + u
    add_kernel<<<(Bsz * Nn) / EW, EW>>>(x, u, xu, Bsz * Nn);
    // 4) c = xu @ A^T - b
    sgemm<true, EPI_SUB_B><<<gBm, blk>>>(xu, A, c, Bsz, Mm, Nn, b);
    // 5) PGD iter 1: lam = relu(step*c), tiled split
    lam_init_tiled<<<(int)(((size_t)Bsz * Mm) / EW), EW>>>(c, lAhi, lAlo);

    // 6) PGD iters 2..50 in ONE persistent launch (49 iterations)
    pgd_persist<<<gT, blk, DSMEM>>>(lAhi, lAlo, lBhi, lBlo, Qhi, Qlo,
                                    c, nullptr, lamf, 49, 0);

    // 7) z = xu - lam @ A
    sgemm<false, EPI_RES><<<gBn, blk>>>(lamf, A, z, Bsz, Nn, Mm, xu);
    // 8) active = (z @ A^T >= b - TOL)
    sgemm<true, EPI_ACTIVE><<<gBm, blk>>>(z, A, act, Bsz, Mm, Nn, b);
    // 9) masked = (u @ A^T) * active
    sgemm<true, EPI_MASKED><<<gBm, blk>>>(u, A, msk, Bsz, Mm, Nn, act);
    // 10) masked PGD iter 1
    lam_init_mask_tiled<<<(int)(((size_t)Bsz * Mm) / EW), EW>>>(msk, act, lAhi, lAlo);

    // 11) masked PGD iters 2..10 in ONE persistent launch (9 iterations)
    pgd_persist<<<gT, blk, DSMEM>>>(lAhi, lAlo, lBhi, lBlo, Qhi, Qlo,
                                    msk, act, lamf, 9, 1);

    // 12) out = u - lam @ A
    sgemm<false, EPI_RES><<<gBn, blk>>>(lamf, A, out, Bsz, Nn, Mm, u);
}

// round 8
// speedup vs baseline: 1.2274x; 1.2274x over previous
#include <cuda_runtime.h>
#include <cuda_bf16.h>
#include <cstddef>
#include <cstdint>

// Problem constants (B=4096, n=512, m=1024)
#define Bsz 4096
#define Nn  512
#define Mm  1024
#define STEPC 0.01f
#define TOLV 1e-5f

// ---- tensor tile config ----
#define TM 128
#define TN 256
#define KC 64
#define TILEA_B 16384          // 128x64 bf16 tile bytes
#define TILEB_B 32768          // 256x64 bf16 tile bytes
#define OFF_ALO 16384
#define OFF_BHI 32768
#define OFF_BLO 65536
#define STG_SZ  98304          // 96 KB per stage
#define DSMEM   (2 * STG_SZ + 1024)

#if defined(__CUDA_ARCH__) && defined(__CUDA_ARCH_FEAT_SM103_ALL)
#define HAS_TCGEN05 1
#else
#define HAS_TCGEN05 0
#endif

// ---------------- device scratch (allocation-free) ----------------
// fp32 linear
__device__ __align__(128) float g_c[(size_t)Bsz * Mm];      // 16 MB
__device__ __align__(128) float g_msk[(size_t)Bsz * Mm];    // 16 MB
__device__ __align__(128) float g_act[(size_t)Bsz * Mm];    // 16 MB
// bf16 hi/lo pre-swizzled tile images
__device__ __align__(128) __nv_bfloat16 g_AAi_h[Mm * Nn];   // A as A-image [8][8]
__device__ __align__(128) __nv_bfloat16 g_AAi_l[Mm * Nn];
__device__ __align__(128) __nv_bfloat16 g_ABi_h[Mm * Nn];   // A as B-image [4][8]
__device__ __align__(128) __nv_bfloat16 g_ABi_l[Mm * Nn];
__device__ __align__(128) __nv_bfloat16 g_ATi_h[Nn * Mm];   // A^T as B-image [2][16]
__device__ __align__(128) __nv_bfloat16 g_ATi_l[Nn * Mm];
__device__ __align__(128) __nv_bfloat16 g_xu_h[(size_t)Bsz * Nn];  // x+u A-image [32][8]
__device__ __align__(128) __nv_bfloat16 g_xu_l[(size_t)Bsz * Nn];
__device__ __align__(128) __nv_bfloat16 g_u_h[(size_t)Bsz * Nn];   // u A-image [32][8]
__device__ __align__(128) __nv_bfloat16 g_u_l[(size_t)Bsz * Nn];
__device__ __align__(128) __nv_bfloat16 g_z_h[(size_t)Bsz * Nn];   // z A-image [32][8]
__device__ __align__(128) __nv_bfloat16 g_z_l[(size_t)Bsz * Nn];
__device__ __align__(128) __nv_bfloat16 g_Qhi[Mm * Mm];     // Q B-image [4][16]
__device__ __align__(128) __nv_bfloat16 g_Qlo[Mm * Mm];
__device__ __align__(128) __nv_bfloat16 g_lAhi[(size_t)Bsz * Mm];  // lam A-images [32][16]
__device__ __align__(128) __nv_bfloat16 g_lAlo[(size_t)Bsz * Mm];
__device__ __align__(128) __nv_bfloat16 g_lBhi[(size_t)Bsz * Mm];
__device__ __align__(128) __nv_bfloat16 g_lBlo[(size_t)Bsz * Mm];

// ---------------- helpers ----------------
__device__ __forceinline__ uint32_t s2u(const void* p) {
    uint32_t a;
    asm("{ .reg .u64 t; cvta.to.shared.u64 t, %1; cvt.u32.u64 %0, t; }"
        : "=r"(a) : "l"(p));
    return a;
}
__device__ __forceinline__ uint32_t swz(uint32_t off) {
    return off ^ ((off >> 3) & 0x70);
}
__device__ __forceinline__ void mbar_init(uint32_t a, uint32_t cnt) {
    asm volatile("mbarrier.init.shared.b64 [%0], %1;" :: "r"(a), "r"(cnt) : "memory");
}
__device__ __forceinline__ void mbar_arrive_tx(uint32_t a, uint32_t bytes) {
    asm volatile("mbarrier.arrive.expect_tx.shared.b64 _, [%0], %1;"
                 :: "r"(a), "r"(bytes) : "memory");
}
__device__ __forceinline__ void mbar_wait(uint32_t a, uint32_t phase) {
    uint32_t done = 0;
    while (!done) {
        asm volatile(
            "{ .reg .pred p; mbarrier.try_wait.parity.shared.b64 p, [%1], %2; "
            "selp.b32 %0, 1, 0, p; }"
            : "=r"(done) : "r"(a), "r"(phase) : "memory");
    }
}
__device__ __forceinline__ void bulk_g2s(uint32_t dst, const void* src,
                                         uint32_t bytes, uint32_t mbar) {
    asm volatile(
        "cp.async.bulk.shared::cluster.global.mbarrier::complete_tx::bytes "
        "[%0], [%1], %2, [%3];"
        :: "r"(dst), "l"(src), "r"(bytes), "r"(mbar) : "memory");
}
__device__ __forceinline__ uint64_t mkdesc(uint32_t addr) {
    return ((uint64_t)2 << 61) | ((uint64_t)1 << 46) | ((uint64_t)64 << 32)
         | ((uint64_t)1 << 16) | ((addr >> 4) & 0x3FFF);
}
#define GEMM_IDESC ((1u<<4) | (1u<<7) | (1u<<10) | ((TN/8)<<17) | ((128/16)<<24))

__device__ __forceinline__ float bfbits2f(uint16_t u) {
    __nv_bfloat16_raw r; r.x = u;
    return __bfloat162float(__nv_bfloat16(r));
}
__device__ __forceinline__ uint16_t f2bfbits(float f) {
    __nv_bfloat16 h = __float2bfloat16(f);
    __nv_bfloat16_raw r = (__nv_bfloat16_raw)h;
    return r.x;
}

#if HAS_TCGEN05
__device__ __forceinline__ void mma_f16_ss(uint32_t d, uint64_t a, uint64_t b,
                                           uint32_t idesc, uint32_t en) {
    asm volatile(
        "{\n\t.reg .pred p;\n\tsetp.ne.u32 p, %5, 0;\n\t"
        "tcgen05.mma.cta_group::1.kind::f16 [%0], %1, %2, %3, {%4,%4,%4,%4}, p;\n\t}"
        :: "r"(d), "l"(a), "l"(b), "r"(idesc), "r"(0u), "r"(en) : "memory");
}
__device__ __forceinline__ void tc_commit(uint32_t mbar) {
    asm volatile(
        "tcgen05.commit.cta_group::1.mbarrier::arrive::one.shared::cluster.b64 [%0];"
        :: "r"(mbar) : "memory");
}
#define TC_ALLOC(sres, n) \
    asm volatile("tcgen05.alloc.cta_group::1.sync.aligned.shared::cta.b32 [%0], %1;" \
                 :: "r"(sres), "r"((uint32_t)(n)) : "memory")
#define TC_RELINQ() \
    asm volatile("tcgen05.relinquish_alloc_permit.cta_group::1.sync.aligned;")
#define TC_DEALLOC(t, n) \
    asm volatile("tcgen05.dealloc.cta_group::1.sync.aligned.b32 %0, %1;" :: "r"(t), "r"((uint32_t)(n)))
#define TC_FENCE_AFTER()  asm volatile("tcgen05.fence::after_thread_sync;" ::: "memory")
#define TC_WAIT_LD()      asm volatile("tcgen05.wait::ld.sync.aligned;" ::: "memory")
#define LDTM_X32(r, a) \
    asm volatile( \
        "tcgen05.ld.sync.aligned.32x32b.x32.b32 " \
        "{%0,%1,%2,%3,%4,%5,%6,%7,%8,%9,%10,%11,%12,%13,%14,%15," \
        "%16,%17,%18,%19,%20,%21,%22,%23,%24,%25,%26,%27,%28,%29,%30,%31}, [%32];" \
        : "=r"((r)[0]),"=r"((r)[1]),"=r"((r)[2]),"=r"((r)[3]), \
          "=r"((r)[4]),"=r"((r)[5]),"=r"((r)[6]),"=r"((r)[7]), \
          "=r"((r)[8]),"=r"((r)[9]),"=r"((r)[10]),"=r"((r)[11]), \
          "=r"((r)[12]),"=r"((r)[13]),"=r"((r)[14]),"=r"((r)[15]), \
          "=r"((r)[16]),"=r"((r)[17]),"=r"((r)[18]),"=r"((r)[19]), \
          "=r"((r)[20]),"=r"((r)[21]),"=r"((r)[22]),"=r"((r)[23]), \
          "=r"((r)[24]),"=r"((r)[25]),"=r"((r)[26]),"=r"((r)[27]), \
          "=r"((r)[28]),"=r"((r)[29]),"=r"((r)[30]),"=r"((r)[31]) \
        : "r"(a))
#endif  // HAS_TCGEN05

// epilogue variants
enum {
    E_PGD = 0,   // v = relu(lamA - step*(acc - v1)) -> images
    E_PGDM,      // same * v2(act)
    E_C,         // c = acc - v1[col]; o32=c; lam=relu(step*c) -> images
    E_ACT,       // o32 = (acc >= v1[col]-TOL) ? 1 : 0
    E_MSK,       // m = acc*v1; o32=m; lam=relu(step*m)*v1 -> images
    E_Z,         // z = v1 + v2 - acc -> images (A-image, Ncols>>6 chunks)
    E_OUT,       // o32 = v1 - acc
    E_Q          // acc -> B-image layout
};

// ---------------------------------------------------------------------------
// Generic tcgen05 GEMM over pre-swizzled tile images, fused epilogues.
//   A-image: [Mtile][nch][128x64 bf16, 16 KB]  (hi + lo)
//   B-image: [Ntile][nch][256x64 bf16, 32 KB]  (hi + lo)
//   acc = Ahi@Bhi^T + Ahi@Blo^T + Alo@Bhi^T  (fp32 TMEM, 128x256 per CTA)
// ---------------------------------------------------------------------------
template <int EPI>
__global__ void __launch_bounds__(256, 1) tc_gemm(
    const __nv_bfloat16* __restrict__ Ahi, const __nv_bfloat16* __restrict__ Alo,
    const __nv_bfloat16* __restrict__ Bhi, const __nv_bfloat16* __restrict__ Blo,
    int nch,
    const float* __restrict__ v1, const float* __restrict__ v2,
    float* __restrict__ o32,
    __nv_bfloat16* __restrict__ ohi, __nv_bfloat16* __restrict__ olo,
    int Ncols)
{
#if HAS_TCGEN05
    extern __shared__ char draw[];
    const uint32_t dsm = (s2u(draw) + 1023u) & ~1023u;

    __shared__ uint32_t s_tmem;
    __shared__ __align__(8) uint64_t s_bar[5];  // f0,f1,e0,e1,done

    const int tid  = threadIdx.x;
    const int wid  = tid >> 5;
    const int lane = tid & 31;
    const int bm0  = blockIdx.y * TM;
    const int bn0  = blockIdx.x * TN;

    const uint32_t f0 = s2u(&s_bar[0]);
    const uint32_t f1 = s2u(&s_bar[1]);
    const uint32_t e0 = s2u(&s_bar[2]);
    const uint32_t e1 = s2u(&s_bar[3]);
    const uint32_t db = s2u(&s_bar[4]);

    if (wid == 0) TC_ALLOC(s2u(&s_tmem), 256);
    if (tid == 0) {
        mbar_init(f0, 1); mbar_init(f1, 1);
        mbar_init(e0, 1); mbar_init(e1, 1);
        mbar_init(db, 1);
    }
    __syncthreads();
    uint32_t tmem;
    asm volatile("ld.shared.b32 %0, [%1];" : "=r"(tmem) : "r"(s2u(&s_tmem)));

    if (tid == 0) {
        const char* aH = (const char*)Ahi + (size_t)blockIdx.y * nch * TILEA_B;
        const char* aL = (const char*)Alo + (size_t)blockIdx.y * nch * TILEA_B;
        const char* bH = (const char*)Bhi + (size_t)blockIdx.x * nch * TILEB_B;
        const char* bL = (const char*)Blo + (size_t)blockIdx.x * nch * TILEB_B;

        auto loadch = [&](int ch) {
            const int s = ch & 1;
            const uint32_t fb = s ? f1 : f0;
            const uint32_t st = dsm + (uint32_t)s * STG_SZ;
            mbar_arrive_tx(fb, (uint32_t)STG_SZ);
            bulk_g2s(st,           aH + (size_t)ch * TILEA_B, TILEA_B, fb);
            bulk_g2s(st + OFF_ALO, aL + (size_t)ch * TILEA_B, TILEA_B, fb);
            bulk_g2s(st + OFF_BHI, bH + (size_t)ch * TILEB_B, TILEB_B, fb);
            bulk_g2s(st + OFF_BLO, bL + (size_t)ch * TILEB_B, TILEB_B, fb);
        };

        loadch(0);
        loadch(1);

        uint32_t phf[2] = {0, 0}, phe[2] = {0, 0};
#pragma unroll 1
        for (int ch = 0; ch < nch; ch++) {
            const int s = ch & 1;
            mbar_wait(s ? f1 : f0, phf[s]); phf[s] ^= 1;

            const uint32_t st = dsm + (uint32_t)s * STG_SZ;
            const uint64_t dah = mkdesc(st);
            const uint64_t dal = mkdesc(st + OFF_ALO);
            const uint64_t dbh = mkdesc(st + OFF_BHI);
            const uint64_t dbl = mkdesc(st + OFF_BLO);
#pragma unroll
            for (int ks = 0; ks < 4; ks++) {
                mma_f16_ss(tmem, dah + ks * 2, dbh + ks * 2, GEMM_IDESC,
                           (ch == 0 && ks == 0) ? 0u : 1u);
                mma_f16_ss(tmem, dah + ks * 2, dbl + ks * 2, GEMM_IDESC, 1u);
                mma_f16_ss(tmem, dal + ks * 2, dbh + ks * 2, GEMM_IDESC, 1u);
            }
            tc_commit(s ? e1 : e0);

            if (ch + 2 < nch) {
                mbar_wait(s ? e1 : e0, phe[s]); phe[s] ^= 1;
                loadch(ch + 2);
            }
        }
        tc_commit(db);
    }

    mbar_wait(db, 0);
    TC_FENCE_AFTER();

    // ---------------- fused epilogue ----------------
    const int sp   = wid & 3;
    const int half = wid >> 2;
    const int lr   = sp * 32 + lane;
    const int r    = bm0 + lr;
    const int nchO = Ncols >> 6;

#pragma unroll 1
    for (int cb = 0; cb < 128; cb += 32) {
        uint32_t dreg[32];
        LDTM_X32(dreg, tmem + half * 128 + cb);
        TC_WAIT_LD();

        const int coff = half * 128 + cb;
        const int gch  = (bn0 + coff) >> 6;
        const int lc0  = coff & 63;
        const size_t blin = (size_t)r * Ncols + bn0 + coff;
        // A-image tile base (lamold read for PGD, image writes for C/MSK/Z)
        const size_t tbA = ((size_t)(blockIdx.y * nchO + gch)) * TILEA_B;
        // B-image tile base (E_Q writes)
        const size_t tbB = ((size_t)((r >> 8) * nchO + gch)) * TILEB_B;
        const int brow = r & 255;

#pragma unroll
        for (int j0 = 0; j0 < 32; j0 += 4) {
            const uint32_t boffA = swz((uint32_t)(lr * 128 + (lc0 + j0) * 2));
            float res[4];
#pragma unroll
            for (int k = 0; k < 4; k++) res[k] = __uint_as_float(dreg[j0 + k]);

            if (EPI == E_PGD || EPI == E_PGDM) {
                float4 cv = *(const float4*)&v1[blin + j0];
                uint64_t h4 = *(const uint64_t*)((const char*)Ahi + tbA + boffA);
                uint64_t l4 = *(const uint64_t*)((const char*)Alo + tbA + boffA);
                float4 av;
                if (EPI == E_PGDM) av = *(const float4*)&v2[blin + j0];
                const float* cvp = (const float*)&cv;
                const float* avp = (const float*)&av;
                uint16_t oh[4], ol[4];
#pragma unroll
                for (int k = 0; k < 4; k++) {
                    float lamold = bfbits2f((uint16_t)(h4 >> (16 * k)))
                                 + bfbits2f((uint16_t)(l4 >> (16 * k)));
                    float v = fmaxf(lamold - STEPC * (res[k] - cvp[k]), 0.f);
                    if (EPI == E_PGDM) v *= avp[k];
                    uint16_t hb = f2bfbits(v);
                    oh[k] = hb; ol[k] = f2bfbits(v - bfbits2f(hb));
                }
                *(uint64_t*)((char*)ohi + tbA + boffA) =
                    (uint64_t)oh[0] | ((uint64_t)oh[1] << 16)
                    | ((uint64_t)oh[2] << 32) | ((uint64_t)oh[3] << 48);
                *(uint64_t*)((char*)olo + tbA + boffA) =
                    (uint64_t)ol[0] | ((uint64_t)ol[1] << 16)
                    | ((uint64_t)ol[2] << 32) | ((uint64_t)ol[3] << 48);
            } else if (EPI == E_C) {
                float4 bv = *(const float4*)&v1[bn0 + coff + j0];
                const float* bp = (const float*)&bv;
                uint16_t oh[4], ol[4];
                float cvv[4];
#pragma unroll
                for (int k = 0; k < 4; k++) {
                    float cv = res[k] - bp[k];
                    cvv[k] = cv;
                    float v = fmaxf(STEPC * cv, 0.f);
                    uint16_t hb = f2bfbits(v);
                    oh[k] = hb; ol[k] = f2bfbits(v - bfbits2f(hb));
                }
                *(float4*)&o32[blin + j0] = make_float4(cvv[0], cvv[1], cvv[2], cvv[3]);
                *(uint64_t*)((char*)ohi + tbA + boffA) =
                    (uint64_t)oh[0] | ((uint64_t)oh[1] << 16)
                    | ((uint64_t)oh[2] << 32) | ((uint64_t)oh[3] << 48);
                *(uint64_t*)((char*)olo + tbA + boffA) =
                    (uint64_t)ol[0] | ((uint64_t)ol[1] << 16)
                    | ((uint64_t)ol[2] << 32) | ((uint64_t)ol[3] << 48);
            } else if (EPI == E_ACT) {
                float4 bv = *(const float4*)&v1[bn0 + coff + j0];
                const float* bp = (const float*)&bv;
                float o[4];
#pragma unroll
                for (int k = 0; k < 4; k++)
                    o[k] = (res[k] >= bp[k] - TOLV) ? 1.f : 0.f;
                *(float4*)&o32[blin + j0] = make_float4(o[0], o[1], o[2], o[3]);
            } else if (EPI == E_MSK) {
                float4 av = *(const float4*)&v1[blin + j0];
                const float* ap = (const float*)&av;
                uint16_t oh[4], ol[4];
                float mm[4];
#pragma unroll
                for (int k = 0; k < 4; k++) {
                    float m = res[k] * ap[k];
                    mm[k] = m;
                    float v = fmaxf(STEPC * m, 0.f) * ap[k];
                    uint16_t hb = f2bfbits(v);
                    oh[k] = hb; ol[k] = f2bfbits(v - bfbits2f(hb));
                }
                *(float4*)&o32[blin + j0] = make_float4(mm[0], mm[1], mm[2], mm[3]);
                *(uint64_t*)((char*)ohi + tbA + boffA) =
                    (uint64_t)oh[0] | ((uint64_t)oh[1] << 16)
                    | ((uint64_t)oh[2] << 32) | ((uint64_t)oh[3] << 48);
                *(uint64_t*)((char*)olo + tbA + boffA) =
                    (uint64_t)ol[0] | ((uint64_t)ol[1] << 16)
                    | ((uint64_t)ol[2] << 32) | ((uint64_t)ol[3] << 48);
            } else if (EPI == E_Z) {
                float4 xv = *(const float4*)&v1[blin + j0];
                float4 uv = *(const float4*)&v2[blin + j0];
                const float* xp = (const float*)&xv;
                const float* up = (const float*)&uv;
                uint16_t oh[4], ol[4];
#pragma unroll
                for (int k = 0; k < 4; k++) {
                    float zv = xp[k] + up[k] - res[k];
                    uint16_t hb = f2bfbits(zv);
                    oh[k] = hb; ol[k] = f2bfbits(zv - bfbits2f(hb));
                }
                *(uint64_t*)((char*)ohi + tbA + boffA) =
                    (uint64_t)oh[0] | ((uint64_t)oh[1] << 16)
                    | ((uint64_t)oh[2] << 32) | ((uint64_t)oh[3] << 48);
                *(uint64_t*)((char*)olo + tbA + boffA) =
                    (uint64_t)ol[0] | ((uint64_t)ol[1] << 16)
                    | ((uint64_t)ol[2] << 32) | ((uint64_t)ol[3] << 48);
            } else if (EPI == E_OUT) {
                float4 uv = *(const float4*)&v1[blin + j0];
                const float* up = (const float*)&uv;
                float o[4];
#pragma unroll
                for (int k = 0; k < 4; k++) o[k] = up[k] - res[k];
                *(float4*)&o32[blin + j0] = make_float4(o[0], o[1], o[2], o[3]);
            } else if (EPI == E_Q) {
                const uint32_t boffB = swz((uint32_t)(brow * 128 + (lc0 + j0) * 2));
                uint16_t oh[4], ol[4];
#pragma unroll
                for (int k = 0; k < 4; k++) {
                    uint16_t hb = f2bfbits(res[k]);
                    oh[k] = hb; ol[k] = f2bfbits(res[k] - bfbits2f(hb));
                }
                *(uint64_t*)((char*)ohi + tbB + boffB) =
                    (uint64_t)oh[0] | ((uint64_t)oh[1] << 16)
                    | ((uint64_t)oh[2] << 32) | ((uint64_t)oh[3] << 48);
                *(uint64_t*)((char*)olo + tbB + boffB) =
                    (uint64_t)ol[0] | ((uint64_t)ol[1] << 16)
                    | ((uint64_t)ol[2] << 32) | ((uint64_t)ol[3] << 48);
            }
        }
    }

    __syncthreads();
    if (wid == 0) { TC_RELINQ(); TC_DEALLOC(tmem, 256); }
#endif  // HAS_TCGEN05
}

// ---------------- prep kernels (one-time splits into tile images) ----------------
__device__ __forceinline__ void img_store(__nv_bfloat16* hi, __nv_bfloat16* lo,
                                          size_t tb, uint32_t boff, float v)
{
    __nv_bfloat16 h = __float2bfloat16(v);
    *(__nv_bfloat16*)((char*)hi + tb + boff) = h;
    *(__nv_bfloat16*)((char*)lo + tb + boff) = __float2bfloat16(v - __bfloat162float(h));
}

// A [1024x512] -> A-image ([8 bm][8 ch]) and B-image ([4 nb][8 ch])
__global__ void split_A_images(const float* __restrict__ A)
{
    int i = blockIdx.x * blockDim.x + threadIdx.x;
    if (i >= Mm * Nn) return;
    int r = i >> 9, k = i & 511;
    float v = A[i];
    int ch = k >> 6, lc = k & 63;
    // A-image
    {
        int bm = r >> 7, lrow = r & 127;
        size_t tb = ((size_t)(bm * 8 + ch)) * TILEA_B;
        img_store(g_AAi_h, g_AAi_l, tb, swz((uint32_t)(lrow * 128 + lc * 2)), v);
    }
    // B-image
    {
        int nb = r >> 8, brow = r & 255;
        size_t tb = ((size_t)(nb * 8 + ch)) * TILEB_B;
        img_store(g_ABi_h, g_ABi_l, tb, swz((uint32_t)(brow * 128 + lc * 2)), v);
    }
}

// A^T [512x1024] -> B-image ([2 nb][16 ch])
__global__ void split_AT_image(const float* __restrict__ A)
{
    int i = blockIdx.x * blockDim.x + threadIdx.x;
    if (i >= Nn * Mm) return;
    int n = i >> 10, k = i & 1023;
    float v = A[(size_t)k * Nn + n];
    int nb = n >> 8, brow = n & 255, ch = k >> 6, lc = k & 63;
    size_t tb = ((size_t)(nb * 16 + ch)) * TILEB_B;
    img_store(g_ATi_h, g_ATi_l, tb, swz((uint32_t)(brow * 128 + lc * 2)), v);
}

// x+u [4096x512] -> A-image ([32 bm][8 ch]);  u -> A-image
__global__ void split_xu_u(const float* __restrict__ x, const float* __restrict__ u)
{
    int i = blockIdx.x * blockDim.x + threadIdx.x;
    if (i >= Bsz * Nn) return;
    int r = i >> 9, k = i & 511;
    int bm = r >> 7, lrow = r & 127, ch = k >> 6, lc = k & 63;
    size_t tb = ((size_t)(bm * 8 + ch)) * TILEA_B;
    uint32_t boff = swz((uint32_t)(lrow * 128 + lc * 2));
    float uv = u[i];
    img_store(g_xu_h, g_xu_l, tb, boff, x[i] + uv);
    img_store(g_u_h,  g_u_l,  tb, boff, uv);
}

// ---------------------------------------------------------------------------
extern "C" void kernel_launch(void* const* d_in, const int* in_sizes, int n_in,
                              void* d_out, int out_size)
{
    const float* x = (const float*)d_in[0];
    const float* u = (const float*)d_in[1];
    const float* A = (const float*)d_in[2];   // [m, n]
    const float* b = (const float*)d_in[3];   // [m]
    float* out = (float*)d_out;

    float *c, *msk, *act;
    __nv_bfloat16 *AAh, *AAl, *ABh, *ABl, *ATh, *ATl, *XUh, *XUl, *Uh, *Ul,
                  *Zh, *Zl, *Qh, *Ql, *lAh, *lAl, *lBh, *lBl;
    cudaGetSymbolAddress((void**)&c,   g_c);
    cudaGetSymbolAddress((void**)&msk, g_msk);
    cudaGetSymbolAddress((void**)&act, g_act);
    cudaGetSymbolAddress((void**)&AAh, g_AAi_h); cudaGetSymbolAddress((void**)&AAl, g_AAi_l);
    cudaGetSymbolAddress((void**)&ABh, g_ABi_h); cudaGetSymbolAddress((void**)&ABl, g_ABi_l);
    cudaGetSymbolAddress((void**)&ATh, g_ATi_h); cudaGetSymbolAddress((void**)&ATl, g_ATi_l);
    cudaGetSymbolAddress((void**)&XUh, g_xu_h);  cudaGetSymbolAddress((void**)&XUl, g_xu_l);
    cudaGetSymbolAddress((void**)&Uh,  g_u_h);   cudaGetSymbolAddress((void**)&Ul,  g_u_l);
    cudaGetSymbolAddress((void**)&Zh,  g_z_h);   cudaGetSymbolAddress((void**)&Zl,  g_z_l);
    cudaGetSymbolAddress((void**)&Qh,  g_Qhi);   cudaGetSymbolAddress((void**)&Ql,  g_Qlo);
    cudaGetSymbolAddress((void**)&lAh, g_lAhi);  cudaGetSymbolAddress((void**)&lAl, g_lAlo);
    cudaGetSymbolAddress((void**)&lBh, g_lBhi);  cudaGetSymbolAddress((void**)&lBl, g_lBlo);

    cudaFuncSetAttribute(tc_gemm<E_PGD>,  cudaFuncAttributeMaxDynamicSharedMemorySize, DSMEM);
    cudaFuncSetAttribute(tc_gemm<E_PGDM>, cudaFuncAttributeMaxDynamicSharedMemorySize, DSMEM);
    cudaFuncSetAttribute(tc_gemm<E_C>,    cudaFuncAttributeMaxDynamicSharedMemorySize, DSMEM);
    cudaFuncSetAttribute(tc_gemm<E_ACT>,  cudaFuncAttributeMaxDynamicSharedMemorySize, DSMEM);
    cudaFuncSetAttribute(tc_gemm<E_MSK>,  cudaFuncAttributeMaxDynamicSharedMemorySize, DSMEM);
    cudaFuncSetAttribute(tc_gemm<E_Z>,    cudaFuncAttributeMaxDynamicSharedMemorySize, DSMEM);
    cudaFuncSetAttribute(tc_gemm<E_OUT>,  cudaFuncAttributeMaxDynamicSharedMemorySize, DSMEM);
    cudaFuncSetAttribute(tc_gemm<E_Q>,    cudaFuncAttributeMaxDynamicSharedMemorySize, DSMEM);

    const dim3 blk(256);
    const int EW = 256;

    // ---- prep: split inputs into tile images ----
    split_A_images<<<(Mm * Nn + EW - 1) / EW, EW>>>(A);
    split_AT_image<<<(Nn * Mm + EW - 1) / EW, EW>>>(A);
    split_xu_u<<<(int)(((size_t)Bsz * Nn + EW - 1) / EW), EW>>>(x, u);

    // ---- Q = A @ A^T -> Q B-images  [M=1024, N=1024, K=512]
    tc_gemm<E_Q><<<dim3(4, 8), blk, DSMEM>>>(AAh, AAl, ABh, ABl, 8,
                                             nullptr, nullptr, nullptr, Qh, Ql, 1024);

    // ---- c = xu @ A^T - b (+ lam init)  [4096, 1024, 512]
    tc_gemm<E_C><<<dim3(4, 32), blk, DSMEM>>>(XUh, XUl, ABh, ABl, 8,
                                              b, nullptr, c, lAh, lAl, 1024);

    // ---- PGD iters 2..50 (49 launches)  [4096, 1024, 1024]
    __nv_bfloat16 *curh = lAh, *curl = lAl, *nxth = lBh, *nxtl = lBl;
    for (int it = 1; it < 50; it++) {
        tc_gemm<E_PGD><<<dim3(4, 32), blk, DSMEM>>>(curh, curl, Qh, Ql, 16,
                                                    c, nullptr, nullptr, nxth, nxtl, 1024);
        __nv_bfloat16* t;
        t = curh; curh = nxth; nxth = t;
        t = curl; curl = nxtl; nxtl = t;
    }

    // ---- z = x + u - lam @ A -> z images  [4096, 512, 1024]
    tc_gemm<E_Z><<<dim3(2, 32), blk, DSMEM>>>(curh, curl, ATh, ATl, 16,
                                              x, u, nullptr, Zh, Zl, 512);

    // ---- active = (z @ A^T >= b - TOL)  [4096, 1024, 512]
    tc_gemm<E_ACT><<<dim3(4, 32), blk, DSMEM>>>(Zh, Zl, ABh, ABl, 8,
                                                b, nullptr, act, nullptr, nullptr, 1024);

    // ---- masked = (u @ A^T) * act (+ masked lam init)  [4096, 1024, 512]
    tc_gemm<E_MSK><<<dim3(4, 32), blk, DSMEM>>>(Uh, Ul, ABh, ABl, 8,
                                                act, nullptr, msk, lAh, lAl, 1024);

    // ---- masked PGD iters 2..10 (9 launches)
    curh = lAh; curl = lAl; nxth = lBh; nxtl = lBl;
    for (int it = 1; it < 10; it++) {
        tc_gemm<E_PGDM><<<dim3(4, 32), blk, DSMEM>>>(curh, curl, Qh, Ql, 16,
                                                     msk, act, nullptr, nxth, nxtl, 1024);
        __nv_bfloat16* t;
        t = curh; curh = nxth; nxth = t;
        t = curl; curl = nxtl; nxtl = t;
    }

    // ---- out = u - lam @ A  [4096, 512, 1024]
    tc_gemm<E_OUT><<<dim3(2, 32), blk, DSMEM>>>(curh, curl, ATh, ATl, 16,
                                                u, nullptr, out, nullptr, nullptr, 512);
}